// round 16
// baseline (speedup 1.0000x reference)
#include <cuda_runtime.h>
#include <cuda_bf16.h>
#include <cstdint>
#include <math.h>

// Problem constants
#define Bb 4
#define Ts 2048
#define Cc 1024
#define Hh 16
#define Dd 64
#define Mtot (Bb*Ts)        // 8192
#define Nqkv (3*Cc)         // 3072
#define Kdim Cc             // 1024

// ---------------------------------------------------------------------------
// Scratch (__device__ globals). RULE: referenced ONLY from device code.
// ---------------------------------------------------------------------------
__device__ __align__(128) __nv_bfloat16 g_xhi[Mtot*Kdim];
__device__ __align__(128) __nv_bfloat16 g_xlo[Mtot*Kdim];
__device__ __align__(128) __nv_bfloat16 g_qhi[Bb*Hh*Ts*Dd];  // [b,h,t,d], pre-scaled 1/8
__device__ __align__(128) __nv_bfloat16 g_qlo[Bb*Hh*Ts*Dd];
__device__ __align__(128) __nv_bfloat16 g_khi[Bb*Hh*Ts*Dd];  // [b,h,t,d]
__device__ __align__(128) __nv_bfloat16 g_klo[Bb*Hh*Ts*Dd];
__device__ __align__(128) __nv_bfloat16 g_vthi[Bb*Hh*Dd*Ts]; // [b,h,d,t] (transposed)
__device__ __align__(128) __nv_bfloat16 g_vtlo[Bb*Hh*Dd*Ts];
__device__ __align__(128) __nv_bfloat16 g_yhi[Mtot*Kdim];
__device__ __align__(128) __nv_bfloat16 g_ylo[Mtot*Kdim];
__device__ __align__(128) __nv_bfloat16 g_wqhi[Nqkv*Kdim];   // [N][K]
__device__ __align__(128) __nv_bfloat16 g_wqlo[Nqkv*Kdim];
__device__ __align__(128) __nv_bfloat16 g_wohi[Cc*Kdim];
__device__ __align__(128) __nv_bfloat16 g_wolo[Cc*Kdim];

// ---------------------------------------------------------------------------
// Helpers
// ---------------------------------------------------------------------------
#define MMA_BF16(c, a, b) asm volatile( \
    "mma.sync.aligned.m16n8k16.row.col.f32.bf16.bf16.f32 " \
    "{%0,%1,%2,%3}, {%4,%5,%6,%7}, {%8,%9}, {%0,%1,%2,%3};" \
    : "+f"((c)[0]), "+f"((c)[1]), "+f"((c)[2]), "+f"((c)[3]) \
    : "r"((a)[0]), "r"((a)[1]), "r"((a)[2]), "r"((a)[3]), \
      "r"((b)[0]), "r"((b)[1]))

#define LDSM4(r, addr) asm volatile( \
    "ldmatrix.sync.aligned.m8n8.x4.shared.b16 {%0,%1,%2,%3}, [%4];" \
    : "=r"((r)[0]), "=r"((r)[1]), "=r"((r)[2]), "=r"((r)[3]) : "r"(addr))

#define CP16(s, g) \
    asm volatile("cp.async.cg.shared.global [%0], [%1], 16;" :: "r"(s), "l"(g))
#define CP_COMMIT() asm volatile("cp.async.commit_group;")
#define CP_WAIT1()  asm volatile("cp.async.wait_group 1;")
#define CP_WAIT0()  asm volatile("cp.async.wait_group 0;")

__device__ __forceinline__ uint32_t smem_to_u32(const void* p) {
    uint32_t a;
    asm("{ .reg .u64 t; cvta.to.shared.u64 t, %1; cvt.u32.u64 %0, t; }"
        : "=r"(a) : "l"(p));
    return a;
}
__device__ __forceinline__ void split2(float a, __nv_bfloat16& h, __nv_bfloat16& l) {
    __nv_bfloat16 hh = __float2bfloat16(a);
    l = __float2bfloat16(a - __bfloat162float(hh));
    h = hh;
}
__device__ __forceinline__ uint32_t pack2(__nv_bfloat16 a, __nv_bfloat16 b) {
    __nv_bfloat162 p = __halves2bfloat162(a, b);
    return *(uint32_t*)&p;
}

// ---------------------------------------------------------------------------
// x pre-split: fp32 -> g_xhi/g_xlo
// ---------------------------------------------------------------------------
__global__ void split_x_kernel(const float* __restrict__ in)
{
    const int i = blockIdx.x * blockDim.x + threadIdx.x;
    float4 v = *(const float4*)&in[(size_t)i * 4];
    __nv_bfloat16 h0,l0,h1,l1,h2,l2,h3,l3;
    split2(v.x, h0, l0); split2(v.y, h1, l1);
    split2(v.z, h2, l2); split2(v.w, h3, l3);
    uint2 hh = make_uint2(pack2(h0, h1), pack2(h2, h3));
    uint2 ll = make_uint2(pack2(l0, l1), pack2(l2, l3));
    *(uint2*)&g_xhi[(size_t)i * 4] = hh;
    *(uint2*)&g_xlo[(size_t)i * 4] = ll;
}

// ---------------------------------------------------------------------------
// Weight transpose + split (proven)
// ---------------------------------------------------------------------------
template<int MODE, int N>
__global__ void transpose_split_kernel(const float* __restrict__ in)
{
    __nv_bfloat16* __restrict__ hi = (MODE == 0) ? g_wqhi : g_wohi;
    __nv_bfloat16* __restrict__ lo = (MODE == 0) ? g_wqlo : g_wolo;

    __shared__ float t[32][33];
    const int n0 = blockIdx.x * 32, k0 = blockIdx.y * 32;
    #pragma unroll
    for (int i = 0; i < 4; i++) {
        int k = k0 + threadIdx.y + i * 8;
        t[threadIdx.y + i * 8][threadIdx.x] = in[(size_t)k * N + n0 + threadIdx.x];
    }
    __syncthreads();
    #pragma unroll
    for (int i = 0; i < 4; i++) {
        int n = n0 + threadIdx.y + i * 8;
        int k = k0 + threadIdx.x;
        __nv_bfloat16 h, l;
        split2(t[threadIdx.x][threadIdx.y + i * 8], h, l);
        hi[(size_t)n * Kdim + k] = h;
        lo[(size_t)n * Kdim + k] = l;
    }
}

#define BM 128
#define BN 128
#define BK 32
#define KPAD 40                    // 80B rows (16B-aligned; bank 20r mod 32 distinct)
#define TILE_E (BM * KPAD)
#define TILE_B (TILE_E * 2)
#define STAGE_E (4 * TILE_E)
#define STAGE_B (4 * TILE_B)
#define GEMM_SMEM (2 * STAGE_B)    // 81920 bytes

// ---------------------------------------------------------------------------
// 3xBF16 warp-MMA GEMM, cp.async pipelined, ldmatrix fragment loads.
// ---------------------------------------------------------------------------
template<int MODE, int N>
__global__ __launch_bounds__(256)
void gemm_mma(const float* __restrict__ bias,
              float* __restrict__ outp)
{
    const __nv_bfloat16* __restrict__ Ahi = (MODE == 0) ? g_xhi : g_yhi;
    const __nv_bfloat16* __restrict__ Alo = (MODE == 0) ? g_xlo : g_ylo;
    const __nv_bfloat16* __restrict__ Bhi = (MODE == 0) ? g_wqhi : g_wohi;
    const __nv_bfloat16* __restrict__ Blo = (MODE == 0) ? g_wqlo : g_wolo;

    extern __shared__ __align__(16) char smem_raw[];
    const uint32_t sbase = smem_to_u32(smem_raw);

    const int tid = threadIdx.x;
    const int l = tid & 31;
    const int wid = tid >> 5;
    const int wm = wid & 3;
    const int wn = wid >> 2;
    const int m0 = blockIdx.y * BM;
    const int n0 = blockIdx.x * BN;
    const int qr = l >> 2;
    const int qc = l & 3;

    // ldmatrix lane addressing: lanes 0-15 -> rows, lanes 16-31 -> +8 cols
    const int lrow = l & 15;
    const int lcol = (l >> 4) << 3;       // 0 or 8 (bf16 cols)

    float acc[2][8][4];
    #pragma unroll
    for (int i = 0; i < 2; i++)
        #pragma unroll
        for (int j = 0; j < 8; j++)
            #pragma unroll
            for (int q = 0; q < 4; q++) acc[i][j][q] = 0.f;

    const int fr = tid >> 2;
    const int fs = (tid & 3) * 8;

    auto issue = [&](int stage, int kc) {
        const int k0 = kc * BK;
        const uint32_t s0 = sbase + (uint32_t)stage * STAGE_B;
        #pragma unroll
        for (int hx = 0; hx < 2; hx++) {
            const int r = fr + hx * 64;
            const uint32_t so = (uint32_t)(r * KPAD + fs) * 2;
            const size_t ga = (size_t)(m0 + r) * Kdim + k0 + fs;
            const size_t gb = (size_t)(n0 + r) * Kdim + k0 + fs;
            CP16(s0 + 0u*TILE_B + so, Ahi + ga);
            CP16(s0 + 1u*TILE_B + so, Alo + ga);
            CP16(s0 + 2u*TILE_B + so, Bhi + gb);
            CP16(s0 + 3u*TILE_B + so, Blo + gb);
        }
        CP_COMMIT();
    };

    const int NC = Kdim / BK;
    issue(0, 0);

    for (int kc = 0; kc < NC; kc++) {
        if (kc + 1 < NC) { issue((kc + 1) & 1, kc + 1); CP_WAIT1(); }
        else             { CP_WAIT0(); }
        __syncthreads();

        const uint32_t stg = sbase + (uint32_t)(kc & 1) * STAGE_B;
        const uint32_t aA0 = stg + 0u*TILE_B;
        const uint32_t aA1 = stg + 1u*TILE_B;
        const uint32_t aB0 = stg + 2u*TILE_B;
        const uint32_t aB1 = stg + 3u*TILE_B;

        #pragma unroll
        for (int kk = 0; kk < 2; kk++) {
            const uint32_t coff = (uint32_t)(kk * 16 + lcol) * 2;

            uint32_t ah[2][4], al[2][4];
            #pragma unroll
            for (int mb = 0; mb < 2; mb++) {
                const uint32_t ro = (uint32_t)((wm * 32 + mb * 16 + lrow) * KPAD) * 2;
                LDSM4(ah[mb], aA0 + ro + coff);
                LDSM4(al[mb], aA1 + ro + coff);
            }
            uint32_t bh[8][2], bl[8][2];
            #pragma unroll
            for (int p = 0; p < 4; p++) {
                const uint32_t ro = (uint32_t)((wn * 64 + p * 16 + lrow) * KPAD) * 2;
                uint32_t t[4];
                LDSM4(t, aB0 + ro + coff);
                bh[2*p][0] = t[0]; bh[2*p+1][0] = t[1];
                bh[2*p][1] = t[2]; bh[2*p+1][1] = t[3];
                LDSM4(t, aB1 + ro + coff);
                bl[2*p][0] = t[0]; bl[2*p+1][0] = t[1];
                bl[2*p][1] = t[2]; bl[2*p+1][1] = t[3];
            }

            #pragma unroll
            for (int mb = 0; mb < 2; mb++)
                #pragma unroll
                for (int nb = 0; nb < 8; nb++)
                    MMA_BF16(acc[mb][nb], ah[mb], bh[nb]);
            #pragma unroll
            for (int mb = 0; mb < 2; mb++)
                #pragma unroll
                for (int nb = 0; nb < 8; nb++)
                    MMA_BF16(acc[mb][nb], ah[mb], bl[nb]);
            #pragma unroll
            for (int mb = 0; mb < 2; mb++)
                #pragma unroll
                for (int nb = 0; nb < 8; nb++)
                    MMA_BF16(acc[mb][nb], al[mb], bh[nb]);
        }
        __syncthreads();
    }

    // ---- epilogue (proven) ----
    #pragma unroll
    for (int mb = 0; mb < 2; mb++) {
        #pragma unroll
        for (int nb = 0; nb < 8; nb++) {
            const int col = wn * 64 + nb * 8 + qc * 2;
            const int n = n0 + col;
            const float bv0 = bias[n];
            const float bv1 = bias[n + 1];
            #pragma unroll
            for (int half = 0; half < 2; half++) {
                const int m = m0 + wm * 32 + mb * 16 + qr + half * 8;
                float v0 = acc[mb][nb][half*2+0] + bv0;
                float v1 = acc[mb][nb][half*2+1] + bv1;
                if (MODE == 0) {
                    const int b = m >> 11, t = m & (Ts - 1);
                    const int which = n >> 10;
                    const int cn = n & (Cc - 1);
                    const int h = cn >> 6, d = cn & 63;
                    const size_t bh_ = (size_t)(b * Hh + h);
                    __nv_bfloat16 h0, l0, h1, l1;
                    if (which == 0) {
                        split2(v0 * 0.125f, h0, l0);
                        split2(v1 * 0.125f, h1, l1);
                        const size_t idx = (bh_ * Ts + t) * Dd + d;
                        *(uint32_t*)&g_qhi[idx] = pack2(h0, h1);
                        *(uint32_t*)&g_qlo[idx] = pack2(l0, l1);
                    } else if (which == 1) {
                        split2(v0, h0, l0);
                        split2(v1, h1, l1);
                        const size_t idx = (bh_ * Ts + t) * Dd + d;
                        *(uint32_t*)&g_khi[idx] = pack2(h0, h1);
                        *(uint32_t*)&g_klo[idx] = pack2(l0, l1);
                    } else {
                        split2(v0, h0, l0);
                        split2(v1, h1, l1);
                        const size_t i0 = (bh_ * Dd + d) * Ts + t;
                        const size_t i1 = (bh_ * Dd + d + 1) * Ts + t;
                        g_vthi[i0] = h0; g_vtlo[i0] = l0;
                        g_vthi[i1] = h1; g_vtlo[i1] = l1;
                    }
                } else {
                    outp[(size_t)m * N + n]     = v0;
                    outp[(size_t)m * N + n + 1] = v1;
                }
            }
        }
    }
}

// ---------------------------------------------------------------------------
// MMA flash attention, cp.async prefetch + ldmatrix fragment loads.
// ---------------------------------------------------------------------------
#define SPAD 72
#define AT_ARR_E (64 * SPAD)
#define AT_ARR_B (AT_ARR_E * 2)
#define AT_STAGE_E (4 * AT_ARR_E)
#define AT_STAGE_B (4 * AT_ARR_B)
#define ATTN_SMEM (2 * AT_STAGE_B)       // 73728 bytes

__global__ __launch_bounds__(128)
void attn_kernel()
{
    extern __shared__ __align__(16) char asmem_raw[];
    const uint32_t sbase = smem_to_u32(asmem_raw);

    const int tid = threadIdx.x;
    const int l = tid & 31;
    const int wm = tid >> 5;
    const int qr = l >> 2;
    const int qc = l & 3;
    const int qt = blockIdx.x;
    const int bh = blockIdx.y;

    const int lrow = l & 15;
    const int lcol = (l >> 4) << 3;

    const size_t qk_base = (size_t)bh * Ts * Dd;
    const size_t vt_base = (size_t)bh * Dd * Ts;

    auto issueKV = [&](int stage, int kt) {
        const uint32_t s0 = sbase + (uint32_t)stage * AT_STAGE_B;
        #pragma unroll
        for (int rep = 0; rep < 4; rep++) {
            const int i = tid + rep * 128;
            const int row = i >> 3;
            const int seg = (i & 7) * 8;
            const uint32_t so = (uint32_t)(row * SPAD + seg) * 2;
            const size_t gk = qk_base + (size_t)(kt * 64 + row) * Dd + seg;
            const size_t gv = vt_base + (size_t)row * Ts + kt * 64 + seg;
            CP16(s0 + 0u*AT_ARR_B + so, g_khi + gk);
            CP16(s0 + 1u*AT_ARR_B + so, g_klo + gk);
            CP16(s0 + 2u*AT_ARR_B + so, g_vthi + gv);
            CP16(s0 + 3u*AT_ARR_B + so, g_vtlo + gv);
        }
        CP_COMMIT();
    };

    uint32_t qh[4][4], ql[4][4];
    {
        const int r0 = qt * 64 + wm * 16 + qr;
        #pragma unroll
        for (int ks = 0; ks < 4; ks++) {
            const int kcol = ks * 16 + qc * 2;
            qh[ks][0] = *(const uint32_t*)&g_qhi[qk_base + (size_t)r0 * Dd + kcol];
            qh[ks][1] = *(const uint32_t*)&g_qhi[qk_base + (size_t)(r0 + 8) * Dd + kcol];
            qh[ks][2] = *(const uint32_t*)&g_qhi[qk_base + (size_t)r0 * Dd + kcol + 8];
            qh[ks][3] = *(const uint32_t*)&g_qhi[qk_base + (size_t)(r0 + 8) * Dd + kcol + 8];
            ql[ks][0] = *(const uint32_t*)&g_qlo[qk_base + (size_t)r0 * Dd + kcol];
            ql[ks][1] = *(const uint32_t*)&g_qlo[qk_base + (size_t)(r0 + 8) * Dd + kcol];
            ql[ks][2] = *(const uint32_t*)&g_qlo[qk_base + (size_t)r0 * Dd + kcol + 8];
            ql[ks][3] = *(const uint32_t*)&g_qlo[qk_base + (size_t)(r0 + 8) * Dd + kcol + 8];
        }
    }

    float o[8][4];
    #pragma unroll
    for (int i = 0; i < 8; i++)
        #pragma unroll
        for (int j = 0; j < 4; j++) o[i][j] = 0.f;
    float m0v = -1e30f, m1v = -1e30f, l0v = 0.f, l1v = 0.f;

    issueKV(0, 0);

    for (int kt = 0; kt <= qt; kt++) {
        if (kt + 1 <= qt) { issueKV((kt + 1) & 1, kt + 1); CP_WAIT1(); }
        else              { CP_WAIT0(); }
        __syncthreads();

        const uint32_t stg = sbase + (uint32_t)(kt & 1) * AT_STAGE_B;
        const uint32_t aKh = stg + 0u*AT_ARR_B;
        const uint32_t aKl = stg + 1u*AT_ARR_B;
        const uint32_t aVh = stg + 2u*AT_ARR_B;
        const uint32_t aVl = stg + 3u*AT_ARR_B;

        // ---- S = Q K^T ----
        float c[8][4];
        #pragma unroll
        for (int nb = 0; nb < 8; nb++)
            #pragma unroll
            for (int q = 0; q < 4; q++) c[nb][q] = 0.f;

        #pragma unroll
        for (int ks = 0; ks < 4; ks++) {
            const uint32_t coff = (uint32_t)(ks * 16 + lcol) * 2;
            uint32_t bhf[8][2], blf[8][2];
            #pragma unroll
            for (int p = 0; p < 4; p++) {
                const uint32_t ro = (uint32_t)((p * 16 + lrow) * SPAD) * 2;
                uint32_t t[4];
                LDSM4(t, aKh + ro + coff);
                bhf[2*p][0] = t[0]; bhf[2*p+1][0] = t[1];
                bhf[2*p][1] = t[2]; bhf[2*p+1][1] = t[3];
                LDSM4(t, aKl + ro + coff);
                blf[2*p][0] = t[0]; blf[2*p+1][0] = t[1];
                blf[2*p][1] = t[2]; blf[2*p+1][1] = t[3];
            }
            #pragma unroll
            for (int nb = 0; nb < 8; nb++) MMA_BF16(c[nb], qh[ks], bhf[nb]);
            #pragma unroll
            for (int nb = 0; nb < 8; nb++) MMA_BF16(c[nb], qh[ks], blf[nb]);
            #pragma unroll
            for (int nb = 0; nb < 8; nb++) MMA_BF16(c[nb], ql[ks], bhf[nb]);
        }

        if (kt == qt) {
            const int r0 = qt * 64 + wm * 16 + qr;
            #pragma unroll
            for (int nb = 0; nb < 8; nb++) {
                const int col = kt * 64 + nb * 8 + qc * 2;
                if (col > r0)     c[nb][0] = -1e30f;
                if (col + 1 > r0) c[nb][1] = -1e30f;
                if (col > r0 + 8)     c[nb][2] = -1e30f;
                if (col + 1 > r0 + 8) c[nb][3] = -1e30f;
            }
        }

        float rmax0 = -1e30f, rmax1 = -1e30f;
        #pragma unroll
        for (int nb = 0; nb < 8; nb++) {
            rmax0 = fmaxf(rmax0, fmaxf(c[nb][0], c[nb][1]));
            rmax1 = fmaxf(rmax1, fmaxf(c[nb][2], c[nb][3]));
        }
        #pragma unroll
        for (int off = 1; off <= 2; off <<= 1) {
            rmax0 = fmaxf(rmax0, __shfl_xor_sync(0xffffffffu, rmax0, off));
            rmax1 = fmaxf(rmax1, __shfl_xor_sync(0xffffffffu, rmax1, off));
        }
        const float mn0 = fmaxf(m0v, rmax0);
        const float mn1 = fmaxf(m1v, rmax1);
        const float cf0 = __expf(m0v - mn0);
        const float cf1 = __expf(m1v - mn1);
        m0v = mn0; m1v = mn1;

        float s0 = 0.f, s1 = 0.f;
        #pragma unroll
        for (int nb = 0; nb < 8; nb++) {
            c[nb][0] = __expf(c[nb][0] - mn0); s0 += c[nb][0];
            c[nb][1] = __expf(c[nb][1] - mn0); s0 += c[nb][1];
            c[nb][2] = __expf(c[nb][2] - mn1); s1 += c[nb][2];
            c[nb][3] = __expf(c[nb][3] - mn1); s1 += c[nb][3];
        }
        #pragma unroll
        for (int off = 1; off <= 2; off <<= 1) {
            s0 += __shfl_xor_sync(0xffffffffu, s0, off);
            s1 += __shfl_xor_sync(0xffffffffu, s1, off);
        }
        l0v = l0v * cf0 + s0;
        l1v = l1v * cf1 + s1;
        #pragma unroll
        for (int i = 0; i < 8; i++) {
            o[i][0] *= cf0; o[i][1] *= cf0;
            o[i][2] *= cf1; o[i][3] *= cf1;
        }

        uint32_t ph[4][4], pl[4][4];
        #pragma unroll
        for (int ks2 = 0; ks2 < 4; ks2++) {
            #pragma unroll
            for (int part = 0; part < 4; part++) {
                const int nb = 2 * ks2 + (part >> 1);
                const int base = (part & 1) * 2;
                const int aidx = (part >> 1) * 2 + (part & 1);
                const float v0 = c[nb][base + 0];
                const float v1 = c[nb][base + 1];
                __nv_bfloat16 h0, lo0, h1, lo1;
                split2(v0, h0, lo0);
                split2(v1, h1, lo1);
                ph[ks2][aidx] = pack2(h0, h1);
                pl[ks2][aidx] = pack2(lo0, lo1);
            }
        }

        // ---- O += P @ V ----
        #pragma unroll
        for (int ks2 = 0; ks2 < 4; ks2++) {
            const uint32_t coff = (uint32_t)(ks2 * 16 + lcol) * 2;
            uint32_t vhf[8][2], vlf[8][2];
            #pragma unroll
            for (int p = 0; p < 4; p++) {
                const uint32_t ro = (uint32_t)((p * 16 + lrow) * SPAD) * 2;
                uint32_t t[4];
                LDSM4(t, aVh + ro + coff);
                vhf[2*p][0] = t[0]; vhf[2*p+1][0] = t[1];
                vhf[2*p][1] = t[2]; vhf[2*p+1][1] = t[3];
                LDSM4(t, aVl + ro + coff);
                vlf[2*p][0] = t[0]; vlf[2*p+1][0] = t[1];
                vlf[2*p][1] = t[2]; vlf[2*p+1][1] = t[3];
            }
            #pragma unroll
            for (int nb2 = 0; nb2 < 8; nb2++) MMA_BF16(o[nb2], ph[ks2], vhf[nb2]);
            #pragma unroll
            for (int nb2 = 0; nb2 < 8; nb2++) MMA_BF16(o[nb2], ph[ks2], vlf[nb2]);
            #pragma unroll
            for (int nb2 = 0; nb2 < 8; nb2++) MMA_BF16(o[nb2], pl[ks2], vhf[nb2]);
        }
        __syncthreads();
    }

    const int b = bh >> 4, h = bh & 15;
    const float inv0 = 1.0f / l0v;
    const float inv1 = 1.0f / l1v;
    const int t0 = qt * 64 + wm * 16 + qr;
    #pragma unroll
    for (int nb2 = 0; nb2 < 8; nb2++) {
        const int d = nb2 * 8 + qc * 2;
        {
            const size_t idx = (size_t)(b * Ts + t0) * Cc + h * Dd + d;
            __nv_bfloat16 h0, lo0, h1, lo1;
            split2(o[nb2][0] * inv0, h0, lo0);
            split2(o[nb2][1] * inv0, h1, lo1);
            *(uint32_t*)&g_yhi[idx] = pack2(h0, h1);
            *(uint32_t*)&g_ylo[idx] = pack2(lo0, lo1);
        }
        {
            const size_t idx = (size_t)(b * Ts + t0 + 8) * Cc + h * Dd + d;
            __nv_bfloat16 h0, lo0, h1, lo1;
            split2(o[nb2][2] * inv1, h0, lo0);
            split2(o[nb2][3] * inv1, h1, lo1);
            *(uint32_t*)&g_yhi[idx] = pack2(h0, h1);
            *(uint32_t*)&g_ylo[idx] = pack2(lo0, lo1);
        }
    }
}

// ---------------------------------------------------------------------------
extern "C" void kernel_launch(void* const* d_in, const int* in_sizes, int n_in,
                              void* d_out, int out_size)
{
    (void)in_sizes; (void)n_in; (void)out_size;
    const float* x     = (const float*)d_in[0];
    const float* w_qkv = (const float*)d_in[1];
    const float* b_qkv = (const float*)d_in[2];
    const float* w_out = (const float*)d_in[3];
    const float* b_out = (const float*)d_in[4];
    float* out = (float*)d_out;

    cudaFuncSetAttribute(gemm_mma<0, Nqkv>,
                         cudaFuncAttributeMaxDynamicSharedMemorySize, GEMM_SMEM);
    cudaFuncSetAttribute(gemm_mma<1, Cc>,
                         cudaFuncAttributeMaxDynamicSharedMemorySize, GEMM_SMEM);
    cudaFuncSetAttribute(attn_kernel,
                         cudaFuncAttributeMaxDynamicSharedMemorySize, ATTN_SMEM);

    // 0) Pre-split x and weights
    split_x_kernel<<<(Mtot*Kdim)/(256*4), 256>>>(x);
    transpose_split_kernel<0, Nqkv><<<dim3(Nqkv/32, Kdim/32), dim3(32,8)>>>(w_qkv);
    transpose_split_kernel<1, Cc><<<dim3(Cc/32, Kdim/32), dim3(32,8)>>>(w_out);

    // 1) QKV projection
    gemm_mma<0, Nqkv><<<dim3(Nqkv/BN, Mtot/BM), 256, GEMM_SMEM>>>(b_qkv, nullptr);

    // 2) MMA flash attention
    attn_kernel<<<dim3(Ts/64, Bb*Hh), 128, ATTN_SMEM>>>();

    // 3) Output projection
    gemm_mma<1, Cc><<<dim3(Cc/BN, Mtot/BM), 256, GEMM_SMEM>>>(b_out, out);
}